// round 16
// baseline (speedup 1.0000x reference)
#include <cuda_runtime.h>
#include <cuda_fp16.h>
#include <math.h>
#include <stdint.h>

#define N_NODES 100000
#define N_EDGES 600000
#define HID 256
#define IN_CH 64
#define SCAN_BLOCKS ((N_NODES + 1023) / 1024)   // 98

// ---------------- scratch (device globals; no allocation allowed) ----------
__device__ __half g_h   [(size_t)N_NODES * HID];   // post-GEMM features (fp16)
__device__ __half g_x   [(size_t)N_NODES * HID];   // activations; also fp16 x copy pre-GEMM1
__device__ __half g_aggx[(size_t)N_NODES * IN_CH]; // layer-1 aggregated input
__device__ __half g_wT1 [HID * IN_CH];             // W1^T [256][64] fp16
__device__ __half g_wT2 [HID * HID];               // W2^T [256][256] fp16
__device__ __half g_wT3 [HID * HID];               // W3^T [256][256] fp16
__device__ float  g_dinv[N_NODES];
__device__ int    g_idg [N_NODES];
__device__ int    g_rowptr[N_NODES + 1];
__device__ int    g_cursor[N_NODES];
__device__ int    g_bsum[SCAN_BLOCKS];
__device__ float2 g_csr [N_EDGES];                 // .x = src (int bits), .y = norm
__device__ int    g_is64;

// ---------------- helpers ----------------------------------------------------
__device__ __forceinline__ void cp16(const void* dstp, const void* src, int srcsz) {
    uint32_t d = (uint32_t)__cvta_generic_to_shared(dstp);
    asm volatile("cp.async.ca.shared.global [%0], [%1], 16, %2;"
                 :: "r"(d), "l"(src), "r"(srcsz));
}

__device__ __forceinline__ void mma_f16(float c[4], const uint32_t a[4],
                                        uint32_t b0, uint32_t b1) {
    asm volatile(
        "mma.sync.aligned.m16n8k16.row.col.f32.f16.f16.f32 "
        "{%0,%1,%2,%3}, {%4,%5,%6,%7}, {%8,%9}, {%0,%1,%2,%3};"
        : "+f"(c[0]), "+f"(c[1]), "+f"(c[2]), "+f"(c[3])
        : "r"(a[0]), "r"(a[1]), "r"(a[2]), "r"(a[3]), "r"(b0), "r"(b1));
}

__device__ __forceinline__ void ldsm4(uint32_t& r0, uint32_t& r1,
                                      uint32_t& r2, uint32_t& r3, uint32_t addr) {
    asm volatile("ldmatrix.sync.aligned.m8n8.x4.shared.b16 {%0,%1,%2,%3}, [%4];"
                 : "=r"(r0), "=r"(r1), "=r"(r2), "=r"(r3) : "r"(addr));
}

// ------- fused front kernel: convert_x | probe+zero | transT (no cross-block
// communication; pure blockIdx dispatch) -------------------------------------
#define CVT_BLOCKS (N_NODES * (IN_CH / 4) / 256)        // 6250
#define PZ_BLOCKS  ((N_NODES + 255) / 256)              // 391
#define TT_BLOCKS  (8 * 8 * 3)                          // 192
#define FRONT_BLOCKS (CVT_BLOCKS + PZ_BLOCKS + TT_BLOCKS)
__global__ __launch_bounds__(256) void front_kernel(
        const float* __restrict__ x, const unsigned int* __restrict__ words,
        const float* __restrict__ W1, const float* __restrict__ W2,
        const float* __restrict__ W3) {
    int b = blockIdx.x;
    int tid = threadIdx.x;
    if (b < CVT_BLOCKS) {
        // ---- x -> fp16 into g_x
        int i = b * 256 + tid;
        float4 v = ((const float4*)x)[i];
        ((__half2*)g_x)[2 * i]     = __floats2half2_rn(v.x, v.y);
        ((__half2*)g_x)[2 * i + 1] = __floats2half2_rn(v.z, v.w);
        return;
    }
    if (b < CVT_BLOCKS + PZ_BLOCKS) {
        int bb = b - CVT_BLOCKS;
        int i = bb * 256 + tid;
        if (i < N_NODES) g_idg[i] = 0;
        if (bb == 0) {
            __shared__ int nz;
            if (tid == 0) nz = 0;
            __syncthreads();
            int local = 0;
            for (int k = tid; k < 1024; k += 256)
                if (words[2 * k + 1] != 0u) local = 1;
            if (local) atomicOr(&nz, 1);
            __syncthreads();
            if (tid == 0) g_is64 = (nz == 0) ? 1 : 0;
        }
        return;
    }
    // ---- weight transpose + fp16
    {
        int bb = b - CVT_BLOCKS - PZ_BLOCKS;
        int z = bb >> 6, rem = bb & 63;
        int by = rem >> 3, bx = rem & 7;
        const float* W = (z == 0) ? W1 : (z == 1) ? W2 : W3;
        __half* dst = (z == 0) ? g_wT1 : (z == 1) ? g_wT2 : g_wT3;
        const int K = (z == 0) ? IN_CH : HID;
        int kb = bx * 32, nb = by * 32;
        if (kb >= K) return;
        __shared__ float t[32][33];
        int tx = tid & 31, ty = tid >> 5;   // 32 x 8
#pragma unroll
        for (int j = 0; j < 32; j += 8)
            t[ty + j][tx] = W[(size_t)(kb + ty + j) * HID + nb + tx];
        __syncthreads();
#pragma unroll
        for (int j = 0; j < 32; j += 8)
            dst[(size_t)(nb + ty + j) * K + kb + tx] = __float2half_rn(t[tx][ty + j]);
    }
}

// ---------------- degree (2 edges per thread) -------------------------------
__global__ void deg_count_kernel(const void* __restrict__ ei) {
    int t = blockIdx.x * blockDim.x + threadIdx.x;
    if (t >= N_EDGES / 2) return;
    int d0, d1;
    if (g_is64) {
        longlong2 p = ((const longlong2*)ei)[N_EDGES / 2 + t];
        d0 = (int)p.x; d1 = (int)p.y;
    } else {
        int2 p = ((const int2*)ei)[N_EDGES / 2 + t];
        d0 = p.x; d1 = p.y;
    }
    atomicAdd(&g_idg[d0], 1);
    atomicAdd(&g_idg[d1], 1);
}

// ---------------- CSR build: scan1 (block-local) + scan23 (fused) -----------
__global__ __launch_bounds__(1024) void scan1_kernel() {
    __shared__ int wsum[32];
    int i = blockIdx.x * 1024 + threadIdx.x;
    int lane = threadIdx.x & 31, wid = threadIdx.x >> 5;
    int v = (i < N_NODES) ? g_idg[i] : 0;
    int s = v;
#pragma unroll
    for (int o = 1; o < 32; o <<= 1) {
        int t = __shfl_up_sync(0xFFFFFFFFu, s, o);
        if (lane >= o) s += t;
    }
    if (lane == 31) wsum[wid] = s;
    __syncthreads();
    if (wid == 0) {
        int ws = wsum[lane];
#pragma unroll
        for (int o = 1; o < 32; o <<= 1) {
            int t = __shfl_up_sync(0xFFFFFFFFu, ws, o);
            if (lane >= o) ws += t;
        }
        wsum[lane] = ws;
    }
    __syncthreads();
    int off = (wid > 0) ? wsum[wid - 1] : 0;
    int incl = s + off;
    if (i < N_NODES) {
        g_rowptr[i] = incl - v;            // exclusive, block-local
        g_dinv[i] = (v > 0) ? rsqrtf((float)v) : 0.0f;
    }
    if (threadIdx.x == 1023) g_bsum[blockIdx.x] = incl;
}

// scan23: each block redundantly prefix-sums the 98 aggregates in smem
// (no cross-block communication), then applies its chunk offset.
__global__ __launch_bounds__(256) void scan23_kernel() {
    __shared__ int sh[128];
    int b = blockIdx.x;                 // 0..PZ_BLOCKS-1 (391)
    int tid = threadIdx.x;
    if (tid < 128) sh[tid] = (tid < SCAN_BLOCKS) ? g_bsum[tid] : 0;
    __syncthreads();
#pragma unroll
    for (int off = 1; off < 128; off <<= 1) {
        int t = (tid < 128 && tid >= off) ? sh[tid - off] : 0;
        __syncthreads();
        if (tid < 128) sh[tid] += t;
        __syncthreads();
    }
    // sh[] now holds INCLUSIVE prefix of bsum
    int i = b * 256 + tid;
    int chunk = i >> 10;                // 256-thread block spans one 1024-chunk
    int boff = (chunk > 0) ? sh[chunk - 1] : 0;
    if (i < N_NODES) {
        int r = g_rowptr[i] + boff;
        g_rowptr[i] = r;
        g_cursor[i] = r;
    }
    if (i == 0) g_rowptr[N_NODES] = N_EDGES;
}

// 2 edges per thread
__global__ void csr_fill_kernel(const void* __restrict__ ei) {
    int t = blockIdx.x * blockDim.x + threadIdx.x;
    if (t >= N_EDGES / 2) return;
    int s0, s1, d0, d1;
    if (g_is64) {
        longlong2 ps = ((const longlong2*)ei)[t];
        longlong2 pd = ((const longlong2*)ei)[N_EDGES / 2 + t];
        s0 = (int)ps.x; s1 = (int)ps.y; d0 = (int)pd.x; d1 = (int)pd.y;
    } else {
        int2 ps = ((const int2*)ei)[t];
        int2 pd = ((const int2*)ei)[N_EDGES / 2 + t];
        s0 = ps.x; s1 = ps.y; d0 = pd.x; d1 = pd.y;
    }
    int p0 = atomicAdd(&g_cursor[d0], 1);
    g_csr[p0] = make_float2(__int_as_float(s0), g_dinv[s0] * g_dinv[d0]);
    int p1 = atomicAdd(&g_cursor[d1], 1);
    g_csr[p1] = make_float2(__int_as_float(s1), g_dinv[s1] * g_dinv[d1]);
}

// ---------------- fp16 tensor GEMM: C[M,256] = A[M,K] @ W[K,256] -------------
// BM=128, BN=128 (gridDim.y=2), BK=32 halves, 3-stage cp.async pipeline,
// one __syncthreads per iteration, LDSM fragment loads.  (R13-proven.)
#define HSTR 40
#define STAGE_B (128 * HSTR * 2)          // 10240 bytes per tile per stage
#define GEMM_SMEM (6 * 128 * HSTR * 2)    // 61440 B
__global__ __launch_bounds__(256, 2) void hgemm_kernel(
        int asel, const float* __restrict__ bias, int csel, int wsel,
        int K, int do_act) {
    const __half* __restrict__ A = (asel == 1) ? g_aggx : g_x;
    const __half* __restrict__ Wt = (wsel == 1) ? g_wT1 : (wsel == 2) ? g_wT2 : g_wT3;
    __half* __restrict__ C = (csel == 1) ? g_h : g_x;
    const int M = N_NODES;

    extern __shared__ __align__(16) __half smem[];
    __half (*As)[128][HSTR] = (__half(*)[128][HSTR])smem;                  // [3]
    __half (*Bs)[128][HSTR] = (__half(*)[128][HSTR])(smem + 3 * 128 * HSTR);

    const int tid  = threadIdx.x;
    const int lane = tid & 31;
    const int warp = tid >> 5;
    const int warpM = warp & 3;
    const int warpN = warp >> 2;
    const int gid = lane >> 2;
    const int lc  = lane & 3;
    const int blockM = blockIdx.x * 128;
    const int blockN = blockIdx.y * 128;

    const int aq = lane >> 3;
    const int arow0 = warpM * 32 + (aq & 1) * 8 + (lane & 7);
    const int acol0 = (aq >> 1) * 8;
    const uint32_t a_base =
        (uint32_t)__cvta_generic_to_shared(&As[0][arow0][acol0]);
    const int bq1 = (lane >> 3) & 1;
    const int bq2 = (lane >> 4) & 1;
    const int brow0 = warpN * 64 + bq2 * 8 + (lane & 7);
    const int bcol0 = bq1 * 8;
    const uint32_t b_base =
        (uint32_t)__cvta_generic_to_shared(&Bs[0][brow0][bcol0]);

    float acc[2][8][4];
#pragma unroll
    for (int i = 0; i < 2; i++)
#pragma unroll
        for (int j = 0; j < 8; j++)
#pragma unroll
            for (int v = 0; v < 4; v++) acc[i][j][v] = 0.0f;

    const int nk = K / 32;

    auto load_stage = [&](int buf, int k0) {
#pragma unroll
        for (int i = 0; i < 2; i++) {
            int idx = tid + i * 256;
            int r = idx >> 2, seg = (idx & 3) * 8;
            int grow = blockM + r;
            const __half* asrc = A + (size_t)((grow < M) ? grow : M - 1) * K + k0 + seg;
            cp16(&As[buf][r][seg], asrc, (grow < M) ? 16 : 0);
            const __half* bsrc = Wt + (size_t)(blockN + r) * K + k0 + seg;
            cp16(&Bs[buf][r][seg], bsrc, 16);
        }
    };

    load_stage(0, 0);
    asm volatile("cp.async.commit_group;" ::: "memory");
    if (nk > 1) load_stage(1, 32);
    asm volatile("cp.async.commit_group;" ::: "memory");

    int buf = 0;
    for (int it = 0; it < nk; it++) {
        asm volatile("cp.async.wait_group 1;" ::: "memory");
        __syncthreads();

        const uint32_t bo = (uint32_t)buf * STAGE_B;
#pragma unroll
        for (int kk = 0; kk < 2; kk++) {
            uint32_t a[2][4];
#pragma unroll
            for (int i = 0; i < 2; i++)
                ldsm4(a[i][0], a[i][1], a[i][2], a[i][3],
                      a_base + bo + i * 1280u + kk * 32u);
#pragma unroll
            for (int j4 = 0; j4 < 4; j4++) {
                uint32_t b0, b1, b2, b3;
                ldsm4(b0, b1, b2, b3, b_base + bo + j4 * 1280u + kk * 32u);
                mma_f16(acc[0][2 * j4],     a[0], b0, b1);
                mma_f16(acc[0][2 * j4 + 1], a[0], b2, b3);
                mma_f16(acc[1][2 * j4],     a[1], b0, b1);
                mma_f16(acc[1][2 * j4 + 1], a[1], b2, b3);
            }
        }

        if (it + 2 < nk) {
            int nbuf = buf + 2; if (nbuf >= 3) nbuf -= 3;
            load_stage(nbuf, (it + 2) * 32);
        }
        asm volatile("cp.async.commit_group;" ::: "memory");

        if (++buf == 3) buf = 0;
    }

    // ---- epilogue: fp32 bias+ELU, round-to-fp16 store
#pragma unroll
    for (int i = 0; i < 2; i++) {
#pragma unroll
        for (int j = 0; j < 8; j++) {
            int col = blockN + warpN * 64 + j * 8 + 2 * lc;
            int row0 = blockM + warpM * 32 + i * 16 + gid;
            int row1 = row0 + 8;
            float v0 = acc[i][j][0], v1 = acc[i][j][1];
            float v2 = acc[i][j][2], v3 = acc[i][j][3];
            if (do_act) {
                float bb0 = bias[col], bb1 = bias[col + 1];
                v0 += bb0; v1 += bb1; v2 += bb0; v3 += bb1;
                v0 = (v0 > 0.f) ? v0 : expm1f(v0);
                v1 = (v1 > 0.f) ? v1 : expm1f(v1);
                v2 = (v2 > 0.f) ? v2 : expm1f(v2);
                v3 = (v3 > 0.f) ? v3 : expm1f(v3);
            }
            if (row0 < M)
                *(__half2*)(C + (size_t)row0 * HID + col) = __floats2half2_rn(v0, v1);
            if (row1 < M)
                *(__half2*)(C + (size_t)row1 * HID + col) = __floats2half2_rn(v2, v3);
        }
    }
}

// ------- CSR gather (256-wide fp16 rows): elu(sum nrm*h[src] + bias) --------
__global__ __launch_bounds__(256) void gather_h_kernel(
        const float* __restrict__ bias, float* __restrict__ extout, int outsel) {
    int w = (blockIdx.x * blockDim.x + threadIdx.x) >> 5;
    if (w >= N_NODES) return;
    int lane = threadIdx.x & 31;
    const int c0 = lane * 8;

    int beg = g_rowptr[w];
    int end = g_rowptr[w + 1];
    float a[8];
#pragma unroll
    for (int j = 0; j < 8; j++) a[j] = 0.0f;

    for (int e = beg; e < end; e++) {
        float2 p = g_csr[e];
        int s = __float_as_int(p.x);
        uint4 rv = *(const uint4*)(g_h + (size_t)s * HID + c0);   // LDG.128
        const __half2* hp = (const __half2*)&rv;
#pragma unroll
        for (int j = 0; j < 4; j++) {
            float2 v = __half22float2(hp[j]);
            a[2 * j]     = fmaf(p.y, v.x, a[2 * j]);
            a[2 * j + 1] = fmaf(p.y, v.y, a[2 * j + 1]);
        }
    }

    float4 b0 = *(const float4*)(bias + c0);
    float4 b1 = *(const float4*)(bias + c0 + 4);
    a[0] += b0.x; a[1] += b0.y; a[2] += b0.z; a[3] += b0.w;
    a[4] += b1.x; a[5] += b1.y; a[6] += b1.z; a[7] += b1.w;
#pragma unroll
    for (int j = 0; j < 8; j++)
        a[j] = (a[j] > 0.f) ? a[j] : expm1f(a[j]);

    if (outsel) {
        __half2 hv[4];
#pragma unroll
        for (int j = 0; j < 4; j++)
            hv[j] = __floats2half2_rn(a[2 * j], a[2 * j + 1]);
        *(uint4*)(g_x + (size_t)w * HID + c0) = *(uint4*)hv;
    } else {
        float* dst = extout + (size_t)w * HID + c0;
        *(float4*)(dst)     = make_float4(a[0], a[1], a[2], a[3]);
        *(float4*)(dst + 4) = make_float4(a[4], a[5], a[6], a[7]);
    }
}

// ------- CSR gather (64-wide, layer 1): g_aggx = A_norm xh  (fp16 in/out) ---
__global__ __launch_bounds__(256) void gather_x_kernel() {
    int w = (blockIdx.x * blockDim.x + threadIdx.x) >> 5;
    if (w >= N_NODES) return;
    int lane = threadIdx.x & 31;

    int beg = g_rowptr[w];
    int end = g_rowptr[w + 1];
    float2 a = make_float2(0.f, 0.f);
    for (int e = beg; e < end; e++) {
        float2 p = g_csr[e];
        int s = __float_as_int(p.x);
        __half2 hv = ((const __half2*)(g_x + (size_t)s * IN_CH))[lane];
        float2 v = __half22float2(hv);
        a.x = fmaf(p.y, v.x, a.x);
        a.y = fmaf(p.y, v.y, a.y);
    }
    *(__half2*)(g_aggx + (size_t)w * IN_CH + 2 * lane) = __floats2half2_rn(a.x, a.y);
}

// ---------------- launch -----------------------------------------------------
extern "C" void kernel_launch(void* const* d_in, const int* in_sizes, int n_in,
                              void* d_out, int out_size) {
    const float* x  = (const float*)d_in[0];
    const void*  ei = d_in[1];
    const float* W1 = (const float*)d_in[2];
    const float* b1 = (const float*)d_in[3];
    const float* W2 = (const float*)d_in[4];
    const float* b2 = (const float*)d_in[5];
    const float* W3 = (const float*)d_in[6];
    const float* b3 = (const float*)d_in[7];
    float* out = (float*)d_out;

    // idempotent attribute set — not a stream op, capture-safe
    cudaFuncSetAttribute(hgemm_kernel,
                         cudaFuncAttributeMaxDynamicSharedMemorySize, GEMM_SMEM);

    const int TPB = 256;
    const int nodeBlocks = (N_NODES + TPB - 1) / TPB;   // 391
    const int edge2Blocks = (N_EDGES / 2 + TPB - 1) / TPB;
    const int warpNodeBlocks = (N_NODES * 32 + TPB - 1) / TPB;
    dim3 gemmGrid((N_NODES + 127) / 128, 2);      // 782 x 2

    // ---- fused front: x->fp16, probe+zero, weight transposes
    front_kernel<<<FRONT_BLOCKS, TPB>>>(x, (const unsigned int*)ei, W1, W2, W3);

    // ---- prep: degree, scan1 + fused scan23, CSR fill
    deg_count_kernel<<<edge2Blocks, TPB>>>(ei);
    scan1_kernel<<<SCAN_BLOCKS, 1024>>>();
    scan23_kernel<<<nodeBlocks, TPB>>>();
    csr_fill_kernel<<<edge2Blocks, TPB>>>(ei);

    // ---- layer 1 (aggregate-first): aggx = A_norm x ; x' = elu(aggx W1 + b1)
    gather_x_kernel<<<warpNodeBlocks, TPB>>>();
    hgemm_kernel<<<gemmGrid, 256, GEMM_SMEM>>>(1, b1, 2, 1, IN_CH, 1);

    // ---- layer 2: h = x' W2 ; x'' = elu(A_norm h + b2)
    hgemm_kernel<<<gemmGrid, 256, GEMM_SMEM>>>(2, nullptr, 1, 2, HID, 0);
    gather_h_kernel<<<warpNodeBlocks, TPB>>>(b2, nullptr, 1);

    // ---- layer 3: h = x'' W3 ; out = elu(A_norm h + b3)
    hgemm_kernel<<<gemmGrid, 256, GEMM_SMEM>>>(2, nullptr, 1, 3, HID, 0);
    gather_h_kernel<<<warpNodeBlocks, TPB>>>(b3, out, 0);
}

// round 17
// speedup vs baseline: 1.0102x; 1.0102x over previous
#include <cuda_runtime.h>
#include <cuda_fp16.h>
#include <math.h>
#include <stdint.h>

#define N_NODES 100000
#define N_EDGES 600000
#define HID 256
#define IN_CH 64
#define SCAN_BLOCKS ((N_NODES + 1023) / 1024)   // 98

// ---------------- scratch (device globals; no allocation allowed) ----------
__device__ __half g_h   [(size_t)N_NODES * HID];   // post-GEMM features (fp16)
__device__ __half g_x   [(size_t)N_NODES * HID];   // activations; also fp16 x copy pre-GEMM1
__device__ __half g_aggx[(size_t)N_NODES * IN_CH]; // layer-1 aggregated input
__device__ __half g_wT1 [HID * IN_CH];             // W1^T [256][64] fp16
__device__ __half g_wT2 [HID * HID];               // W2^T [256][256] fp16
__device__ __half g_wT3 [HID * HID];               // W3^T [256][256] fp16
__device__ float  g_dinv[N_NODES];
__device__ int    g_idg [N_NODES];
__device__ int    g_rowptr[N_NODES + 1];
__device__ int    g_cursor[N_NODES];
__device__ int    g_bsum[SCAN_BLOCKS];
__device__ int    g_boff[SCAN_BLOCKS];
__device__ float2 g_csr [N_EDGES];                 // .x = src (int bits), .y = norm
__device__ int    g_is64;

// ---------------- helpers ----------------------------------------------------
__device__ __forceinline__ void cp16(const void* dstp, const void* src, int srcsz) {
    uint32_t d = (uint32_t)__cvta_generic_to_shared(dstp);
    asm volatile("cp.async.ca.shared.global [%0], [%1], 16, %2;"
                 :: "r"(d), "l"(src), "r"(srcsz));
}

__device__ __forceinline__ void mma_f16(float c[4], const uint32_t a[4],
                                        uint32_t b0, uint32_t b1) {
    asm volatile(
        "mma.sync.aligned.m16n8k16.row.col.f32.f16.f16.f32 "
        "{%0,%1,%2,%3}, {%4,%5,%6,%7}, {%8,%9}, {%0,%1,%2,%3};"
        : "+f"(c[0]), "+f"(c[1]), "+f"(c[2]), "+f"(c[3])
        : "r"(a[0]), "r"(a[1]), "r"(a[2]), "r"(a[3]), "r"(b0), "r"(b1));
}

__device__ __forceinline__ void ldsm4(uint32_t& r0, uint32_t& r1,
                                      uint32_t& r2, uint32_t& r3, uint32_t addr) {
    asm volatile("ldmatrix.sync.aligned.m8n8.x4.shared.b16 {%0,%1,%2,%3}, [%4];"
                 : "=r"(r0), "=r"(r1), "=r"(r2), "=r"(r3) : "r"(addr));
}

// ------- probe (block 0) + zero degree: prep-chain head ---------------------
__global__ void probe_zero_kernel(const unsigned int* __restrict__ words) {
    int i = blockIdx.x * blockDim.x + threadIdx.x;
    if (i < N_NODES) g_idg[i] = 0;
    if (blockIdx.x == 0) {
        __shared__ int nz;
        if (threadIdx.x == 0) nz = 0;
        __syncthreads();
        int local = 0;
        for (int k = threadIdx.x; k < 1024; k += blockDim.x)
            if (words[2 * k + 1] != 0u) local = 1;
        if (local) atomicOr(&nz, 1);
        __syncthreads();
        if (threadIdx.x == 0) g_is64 = (nz == 0) ? 1 : 0;
    }
}

// ------- side kernel (parallel branch): convert_x | transT ------------------
#define CVT_BLOCKS (N_NODES * (IN_CH / 4) / 256)        // 6250
#define TT_BLOCKS  (8 * 8 * 3)                          // 192
#define SIDE_BLOCKS (CVT_BLOCKS + TT_BLOCKS)
__global__ __launch_bounds__(256) void side_kernel(
        const float* __restrict__ x, const float* __restrict__ W1,
        const float* __restrict__ W2, const float* __restrict__ W3) {
    int b = blockIdx.x;
    int tid = threadIdx.x;
    if (b < CVT_BLOCKS) {
        int i = b * 256 + tid;
        float4 v = ((const float4*)x)[i];
        ((__half2*)g_x)[2 * i]     = __floats2half2_rn(v.x, v.y);
        ((__half2*)g_x)[2 * i + 1] = __floats2half2_rn(v.z, v.w);
        return;
    }
    {
        int bb = b - CVT_BLOCKS;
        int z = bb >> 6, rem = bb & 63;
        int by = rem >> 3, bx = rem & 7;
        const float* W = (z == 0) ? W1 : (z == 1) ? W2 : W3;
        __half* dst = (z == 0) ? g_wT1 : (z == 1) ? g_wT2 : g_wT3;
        const int K = (z == 0) ? IN_CH : HID;
        int kb = bx * 32, nb = by * 32;
        if (kb >= K) return;
        __shared__ float t[32][33];
        int tx = tid & 31, ty = tid >> 5;   // 32 x 8
#pragma unroll
        for (int j = 0; j < 32; j += 8)
            t[ty + j][tx] = W[(size_t)(kb + ty + j) * HID + nb + tx];
        __syncthreads();
#pragma unroll
        for (int j = 0; j < 32; j += 8)
            dst[(size_t)(nb + ty + j) * K + kb + tx] = __float2half_rn(t[tx][ty + j]);
    }
}

// ---------------- degree (2 edges per thread) -------------------------------
__global__ void deg_count_kernel(const void* __restrict__ ei) {
    int t = blockIdx.x * blockDim.x + threadIdx.x;
    if (t >= N_EDGES / 2) return;
    int d0, d1;
    if (g_is64) {
        longlong2 p = ((const longlong2*)ei)[N_EDGES / 2 + t];
        d0 = (int)p.x; d1 = (int)p.y;
    } else {
        int2 p = ((const int2*)ei)[N_EDGES / 2 + t];
        d0 = p.x; d1 = p.y;
    }
    atomicAdd(&g_idg[d0], 1);
    atomicAdd(&g_idg[d1], 1);
}

// ---------------- CSR build (3-phase scan, proven; scan1 emits dinv) --------
__global__ __launch_bounds__(1024) void scan1_kernel() {
    __shared__ int wsum[32];
    int i = blockIdx.x * 1024 + threadIdx.x;
    int lane = threadIdx.x & 31, wid = threadIdx.x >> 5;
    int v = (i < N_NODES) ? g_idg[i] : 0;
    int s = v;
#pragma unroll
    for (int o = 1; o < 32; o <<= 1) {
        int t = __shfl_up_sync(0xFFFFFFFFu, s, o);
        if (lane >= o) s += t;
    }
    if (lane == 31) wsum[wid] = s;
    __syncthreads();
    if (wid == 0) {
        int ws = wsum[lane];
#pragma unroll
        for (int o = 1; o < 32; o <<= 1) {
            int t = __shfl_up_sync(0xFFFFFFFFu, ws, o);
            if (lane >= o) ws += t;
        }
        wsum[lane] = ws;
    }
    __syncthreads();
    int off = (wid > 0) ? wsum[wid - 1] : 0;
    int incl = s + off;
    if (i < N_NODES) {
        g_rowptr[i] = incl - v;            // exclusive, block-local
        g_dinv[i] = (v > 0) ? rsqrtf((float)v) : 0.0f;
    }
    if (threadIdx.x == 1023) g_bsum[blockIdx.x] = incl;
}

__global__ void scan2_kernel() {
    __shared__ int sh[SCAN_BLOCKS];
    int tid = threadIdx.x;
    if (tid < SCAN_BLOCKS) sh[tid] = g_bsum[tid];
    __syncthreads();
    if (tid == 0) {
        int acc = 0;
        for (int b = 0; b < SCAN_BLOCKS; b++) { int t = sh[b]; sh[b] = acc; acc += t; }
    }
    __syncthreads();
    if (tid < SCAN_BLOCKS) g_boff[tid] = sh[tid];
}

__global__ void scan3_kernel() {
    int i = blockIdx.x * blockDim.x + threadIdx.x;
    if (i < N_NODES) {
        int r = g_rowptr[i] + g_boff[i >> 10];
        g_rowptr[i] = r;
        g_cursor[i] = r;
    }
    if (i == 0) g_rowptr[N_NODES] = N_EDGES;
}

// 2 edges per thread
__global__ void csr_fill_kernel(const void* __restrict__ ei) {
    int t = blockIdx.x * blockDim.x + threadIdx.x;
    if (t >= N_EDGES / 2) return;
    int s0, s1, d0, d1;
    if (g_is64) {
        longlong2 ps = ((const longlong2*)ei)[t];
        longlong2 pd = ((const longlong2*)ei)[N_EDGES / 2 + t];
        s0 = (int)ps.x; s1 = (int)ps.y; d0 = (int)pd.x; d1 = (int)pd.y;
    } else {
        int2 ps = ((const int2*)ei)[t];
        int2 pd = ((const int2*)ei)[N_EDGES / 2 + t];
        s0 = ps.x; s1 = ps.y; d0 = pd.x; d1 = pd.y;
    }
    int p0 = atomicAdd(&g_cursor[d0], 1);
    g_csr[p0] = make_float2(__int_as_float(s0), g_dinv[s0] * g_dinv[d0]);
    int p1 = atomicAdd(&g_cursor[d1], 1);
    g_csr[p1] = make_float2(__int_as_float(s1), g_dinv[s1] * g_dinv[d1]);
}

// ---------------- fp16 tensor GEMM: C[M,256] = A[M,K] @ W[K,256] -------------
// BM=128, BN=128 (gridDim.y=2), BK=32 halves, 3-stage cp.async pipeline,
// one __syncthreads per iteration, LDSM fragment loads.  (R13-proven.)
#define HSTR 40
#define STAGE_B (128 * HSTR * 2)          // 10240 bytes per tile per stage
#define GEMM_SMEM (6 * 128 * HSTR * 2)    // 61440 B
__global__ __launch_bounds__(256, 2) void hgemm_kernel(
        int asel, const float* __restrict__ bias, int csel, int wsel,
        int K, int do_act) {
    const __half* __restrict__ A = (asel == 1) ? g_aggx : g_x;
    const __half* __restrict__ Wt = (wsel == 1) ? g_wT1 : (wsel == 2) ? g_wT2 : g_wT3;
    __half* __restrict__ C = (csel == 1) ? g_h : g_x;
    const int M = N_NODES;

    extern __shared__ __align__(16) __half smem[];
    __half (*As)[128][HSTR] = (__half(*)[128][HSTR])smem;                  // [3]
    __half (*Bs)[128][HSTR] = (__half(*)[128][HSTR])(smem + 3 * 128 * HSTR);

    const int tid  = threadIdx.x;
    const int lane = tid & 31;
    const int warp = tid >> 5;
    const int warpM = warp & 3;
    const int warpN = warp >> 2;
    const int gid = lane >> 2;
    const int lc  = lane & 3;
    const int blockM = blockIdx.x * 128;
    const int blockN = blockIdx.y * 128;

    const int aq = lane >> 3;
    const int arow0 = warpM * 32 + (aq & 1) * 8 + (lane & 7);
    const int acol0 = (aq >> 1) * 8;
    const uint32_t a_base =
        (uint32_t)__cvta_generic_to_shared(&As[0][arow0][acol0]);
    const int bq1 = (lane >> 3) & 1;
    const int bq2 = (lane >> 4) & 1;
    const int brow0 = warpN * 64 + bq2 * 8 + (lane & 7);
    const int bcol0 = bq1 * 8;
    const uint32_t b_base =
        (uint32_t)__cvta_generic_to_shared(&Bs[0][brow0][bcol0]);

    float acc[2][8][4];
#pragma unroll
    for (int i = 0; i < 2; i++)
#pragma unroll
        for (int j = 0; j < 8; j++)
#pragma unroll
            for (int v = 0; v < 4; v++) acc[i][j][v] = 0.0f;

    const int nk = K / 32;

    auto load_stage = [&](int buf, int k0) {
#pragma unroll
        for (int i = 0; i < 2; i++) {
            int idx = tid + i * 256;
            int r = idx >> 2, seg = (idx & 3) * 8;
            int grow = blockM + r;
            const __half* asrc = A + (size_t)((grow < M) ? grow : M - 1) * K + k0 + seg;
            cp16(&As[buf][r][seg], asrc, (grow < M) ? 16 : 0);
            const __half* bsrc = Wt + (size_t)(blockN + r) * K + k0 + seg;
            cp16(&Bs[buf][r][seg], bsrc, 16);
        }
    };

    load_stage(0, 0);
    asm volatile("cp.async.commit_group;" ::: "memory");
    if (nk > 1) load_stage(1, 32);
    asm volatile("cp.async.commit_group;" ::: "memory");

    int buf = 0;
    for (int it = 0; it < nk; it++) {
        asm volatile("cp.async.wait_group 1;" ::: "memory");
        __syncthreads();

        const uint32_t bo = (uint32_t)buf * STAGE_B;
#pragma unroll
        for (int kk = 0; kk < 2; kk++) {
            uint32_t a[2][4];
#pragma unroll
            for (int i = 0; i < 2; i++)
                ldsm4(a[i][0], a[i][1], a[i][2], a[i][3],
                      a_base + bo + i * 1280u + kk * 32u);
#pragma unroll
            for (int j4 = 0; j4 < 4; j4++) {
                uint32_t b0, b1, b2, b3;
                ldsm4(b0, b1, b2, b3, b_base + bo + j4 * 1280u + kk * 32u);
                mma_f16(acc[0][2 * j4],     a[0], b0, b1);
                mma_f16(acc[0][2 * j4 + 1], a[0], b2, b3);
                mma_f16(acc[1][2 * j4],     a[1], b0, b1);
                mma_f16(acc[1][2 * j4 + 1], a[1], b2, b3);
            }
        }

        if (it + 2 < nk) {
            int nbuf = buf + 2; if (nbuf >= 3) nbuf -= 3;
            load_stage(nbuf, (it + 2) * 32);
        }
        asm volatile("cp.async.commit_group;" ::: "memory");

        if (++buf == 3) buf = 0;
    }

    // ---- epilogue: fp32 bias+ELU, round-to-fp16 store
#pragma unroll
    for (int i = 0; i < 2; i++) {
#pragma unroll
        for (int j = 0; j < 8; j++) {
            int col = blockN + warpN * 64 + j * 8 + 2 * lc;
            int row0 = blockM + warpM * 32 + i * 16 + gid;
            int row1 = row0 + 8;
            float v0 = acc[i][j][0], v1 = acc[i][j][1];
            float v2 = acc[i][j][2], v3 = acc[i][j][3];
            if (do_act) {
                float bb0 = bias[col], bb1 = bias[col + 1];
                v0 += bb0; v1 += bb1; v2 += bb0; v3 += bb1;
                v0 = (v0 > 0.f) ? v0 : expm1f(v0);
                v1 = (v1 > 0.f) ? v1 : expm1f(v1);
                v2 = (v2 > 0.f) ? v2 : expm1f(v2);
                v3 = (v3 > 0.f) ? v3 : expm1f(v3);
            }
            if (row0 < M)
                *(__half2*)(C + (size_t)row0 * HID + col) = __floats2half2_rn(v0, v1);
            if (row1 < M)
                *(__half2*)(C + (size_t)row1 * HID + col) = __floats2half2_rn(v2, v3);
        }
    }
}

// ------- CSR gather (256-wide fp16 rows): elu(sum nrm*h[src] + bias) --------
__global__ __launch_bounds__(256) void gather_h_kernel(
        const float* __restrict__ bias, float* __restrict__ extout, int outsel) {
    int w = (blockIdx.x * blockDim.x + threadIdx.x) >> 5;
    if (w >= N_NODES) return;
    int lane = threadIdx.x & 31;
    const int c0 = lane * 8;

    int beg = g_rowptr[w];
    int end = g_rowptr[w + 1];
    float a[8];
#pragma unroll
    for (int j = 0; j < 8; j++) a[j] = 0.0f;

    for (int e = beg; e < end; e++) {
        float2 p = g_csr[e];
        int s = __float_as_int(p.x);
        uint4 rv = *(const uint4*)(g_h + (size_t)s * HID + c0);   // LDG.128
        const __half2* hp = (const __half2*)&rv;
#pragma unroll
        for (int j = 0; j < 4; j++) {
            float2 v = __half22float2(hp[j]);
            a[2 * j]     = fmaf(p.y, v.x, a[2 * j]);
            a[2 * j + 1] = fmaf(p.y, v.y, a[2 * j + 1]);
        }
    }

    float4 b0 = *(const float4*)(bias + c0);
    float4 b1 = *(const float4*)(bias + c0 + 4);
    a[0] += b0.x; a[1] += b0.y; a[2] += b0.z; a[3] += b0.w;
    a[4] += b1.x; a[5] += b1.y; a[6] += b1.z; a[7] += b1.w;
#pragma unroll
    for (int j = 0; j < 8; j++)
        a[j] = (a[j] > 0.f) ? a[j] : expm1f(a[j]);

    if (outsel) {
        __half2 hv[4];
#pragma unroll
        for (int j = 0; j < 4; j++)
            hv[j] = __floats2half2_rn(a[2 * j], a[2 * j + 1]);
        *(uint4*)(g_x + (size_t)w * HID + c0) = *(uint4*)hv;
    } else {
        float* dst = extout + (size_t)w * HID + c0;
        *(float4*)(dst)     = make_float4(a[0], a[1], a[2], a[3]);
        *(float4*)(dst + 4) = make_float4(a[4], a[5], a[6], a[7]);
    }
}

// ------- CSR gather (64-wide, layer 1): g_aggx = A_norm xh  (fp16 in/out) ---
__global__ __launch_bounds__(256) void gather_x_kernel() {
    int w = (blockIdx.x * blockDim.x + threadIdx.x) >> 5;
    if (w >= N_NODES) return;
    int lane = threadIdx.x & 31;

    int beg = g_rowptr[w];
    int end = g_rowptr[w + 1];
    float2 a = make_float2(0.f, 0.f);
    for (int e = beg; e < end; e++) {
        float2 p = g_csr[e];
        int s = __float_as_int(p.x);
        __half2 hv = ((const __half2*)(g_x + (size_t)s * IN_CH))[lane];
        float2 v = __half22float2(hv);
        a.x = fmaf(p.y, v.x, a.x);
        a.y = fmaf(p.y, v.y, a.y);
    }
    *(__half2*)(g_aggx + (size_t)w * IN_CH + 2 * lane) = __floats2half2_rn(a.x, a.y);
}

// ---------------- launch -----------------------------------------------------
extern "C" void kernel_launch(void* const* d_in, const int* in_sizes, int n_in,
                              void* d_out, int out_size) {
    const float* x  = (const float*)d_in[0];
    const void*  ei = d_in[1];
    const float* W1 = (const float*)d_in[2];
    const float* b1 = (const float*)d_in[3];
    const float* W2 = (const float*)d_in[4];
    const float* b2 = (const float*)d_in[5];
    const float* W3 = (const float*)d_in[6];
    const float* b3 = (const float*)d_in[7];
    float* out = (float*)d_out;

    // idempotent attribute set — not a stream op, capture-safe
    cudaFuncSetAttribute(hgemm_kernel,
                         cudaFuncAttributeMaxDynamicSharedMemorySize, GEMM_SMEM);

    // side stream + events: created once on the FIRST call (the correctness
    // run, which is NOT captured), reused thereafter. No per-call resource
    // creation during graph capture.
    static cudaStream_t s_side = nullptr;
    static cudaEvent_t  s_fork = nullptr, s_join = nullptr;
    if (s_side == nullptr) {
        cudaStreamCreateWithFlags(&s_side, cudaStreamNonBlocking);
        cudaEventCreateWithFlags(&s_fork, cudaEventDisableTiming);
        cudaEventCreateWithFlags(&s_join, cudaEventDisableTiming);
    }

    const int TPB = 256;
    const int nodeBlocks = (N_NODES + TPB - 1) / TPB;
    const int edge2Blocks = (N_EDGES / 2 + TPB - 1) / TPB;
    const int warpNodeBlocks = (N_NODES * 32 + TPB - 1) / TPB;
    dim3 gemmGrid((N_NODES + 127) / 128, 2);      // 782 x 2

    // ---- fork: side branch does x->fp16 + weight transposes
    cudaEventRecord(s_fork, 0);
    cudaStreamWaitEvent(s_side, s_fork, 0);
    side_kernel<<<SIDE_BLOCKS, TPB, 0, s_side>>>(x, W1, W2, W3);
    cudaEventRecord(s_join, s_side);

    // ---- main branch: probe+zero, degree, 3-phase scan, CSR fill
    probe_zero_kernel<<<nodeBlocks, TPB>>>((const unsigned int*)ei);
    deg_count_kernel<<<edge2Blocks, TPB>>>(ei);
    scan1_kernel<<<SCAN_BLOCKS, 1024>>>();
    scan2_kernel<<<1, 128>>>();
    scan3_kernel<<<nodeBlocks, TPB>>>();
    csr_fill_kernel<<<edge2Blocks, TPB>>>(ei);

    // ---- join: gather_x needs g_x (side) + CSR (main); GEMM1 needs g_wT1
    cudaStreamWaitEvent(0, s_join, 0);

    // ---- layer 1 (aggregate-first): aggx = A_norm x ; x' = elu(aggx W1 + b1)
    gather_x_kernel<<<warpNodeBlocks, TPB>>>();
    hgemm_kernel<<<gemmGrid, 256, GEMM_SMEM>>>(1, b1, 2, 1, IN_CH, 1);

    // ---- layer 2: h = x' W2 ; x'' = elu(A_norm h + b2)
    hgemm_kernel<<<gemmGrid, 256, GEMM_SMEM>>>(2, nullptr, 1, 2, HID, 0);
    gather_h_kernel<<<warpNodeBlocks, TPB>>>(b2, nullptr, 1);

    // ---- layer 3: h = x'' W3 ; out = elu(A_norm h + b3)
    hgemm_kernel<<<gemmGrid, 256, GEMM_SMEM>>>(2, nullptr, 1, 3, HID, 0);
    gather_h_kernel<<<warpNodeBlocks, TPB>>>(b3, out, 0);
}